// round 9
// baseline (speedup 1.0000x reference)
#include <cuda_runtime.h>
#include <cuda_bf16.h>
#include <cstdint>

#define NUM_USERS 200000
#define NUM_ITEMS 100000
#define NUM_NODES (NUM_USERS + NUM_ITEMS)
#define NUM_EDGES 600000
#define DIM 128
#define BATCH 16384
#define BPB 128
#define S 132   // smem row stride (floats): conflict-free fragment access

// ---------------- scratch (static device globals) ---------------------------
// INVARIANT: g_mask is all-zero at entry to every kernel_launch call.
// (Zero-initialized at load; k_pairs clears every bit it set, every call.)
__device__ __align__(16) float g_agg[(size_t)NUM_NODES * DIM];
__device__ __align__(16) unsigned char g_mask[NUM_NODES];
__device__ __align__(16) float g_M[DIM * DIM];      // W^T W, tf32-rounded (symmetric)
__device__ __align__(16) float g_v[DIM];            // W^T b (fp32)
__device__ float g_c;                               // b.b

__device__ __forceinline__ float tf32r(float x) {
    unsigned u = __float_as_uint(x);
    u = (u + 0x1000u) & 0xFFFFE000u;
    return __uint_as_float(u);
}

// ---------------- K0 (fused): precompute + mark/zero rows --------------------
// blocks [0,64):          M rows 2b, 2b+1 (tf32), block 0 also v and c
// blocks [64, 64+4096):   mark needed nodes + zero their agg rows
#define MBLOCKS 64
#define MARKBLOCKS ((2 * BATCH * 32) / 256)     // 4096
#define PREGRID (MBLOCKS + MARKBLOCKS)
__global__ void k_pre(const float* __restrict__ W, const float* __restrict__ b,
                      const int* __restrict__ ui, const int* __restrict__ ii) {
    int blk = blockIdx.x, tid = threadIdx.x;
    if (blk < MBLOCKS) {
        int r = 2 * blk + (tid >> 7);
        int c = tid & 127;
        float acc = 0.f;
#pragma unroll 8
        for (int j = 0; j < DIM; j++)
            acc += W[j * DIM + r] * W[j * DIM + c];
        g_M[r * DIM + c] = tf32r(acc);
        if (blk == 0 && tid < 128) {
            float vv = 0.f;
#pragma unroll 8
            for (int j = 0; j < DIM; j++) vv += b[j] * W[j * DIM + c];
            g_v[c] = vv;
            if (tid == 0) {
                float s = 0.f;
#pragma unroll 8
                for (int j = 0; j < DIM; j++) s += b[j] * b[j];
                g_c = s;
            }
        }
    } else {
        int t = (blk - MBLOCKS) * 256 + tid;
        int ref = t >> 5, sub = t & 31;
        int node = (ref < BATCH) ? __ldg(&ui[ref]) : (NUM_USERS + __ldg(&ii[ref - BATCH]));
        ((float4*)(g_agg + (size_t)node * DIM))[sub] = make_float4(0.f, 0.f, 0.f, 0.f);
        if (sub == 0) g_mask[node] = 1;
    }
}

// ---------------- K1: scan edges, gather + vectorized scatter-add ------------
__global__ void k_edge(const int* __restrict__ src, const int* __restrict__ dst,
                       const float* __restrict__ uemb, const float* __restrict__ iemb) {
    int e = blockIdx.x * blockDim.x + threadIdx.x;
    int lane = threadIdx.x & 31;
    bool pass = false;
    int d = 0, s = 0;
    if (e < NUM_EDGES) {
        d = dst[e];
        pass = (g_mask[d] != 0);
        if (pass) s = src[e];
    }
    unsigned m = __ballot_sync(0xffffffffu, pass);
    while (m) {
        int bit = __ffs(m) - 1;
        m &= m - 1;
        int ds = __shfl_sync(0xffffffffu, d, bit);
        int ss = __shfl_sync(0xffffffffu, s, bit);
        const float* sp = (ss < NUM_USERS)
                            ? (uemb + (size_t)ss * DIM)
                            : (iemb + (size_t)(ss - NUM_USERS) * DIM);
        float4 v = ((const float4*)sp)[lane];
        float* a = g_agg + (size_t)ds * DIM + lane * 4;
        asm volatile("red.global.add.v4.f32 [%0], {%1, %2, %3, %4};"
                     :: "l"(a), "f"(v.x), "f"(v.y), "f"(v.z), "f"(v.w)
                     : "memory");
    }
}

// ---------------- K2: mma.sync tf32 GEMM + fused bilinear epilogue -----------
// Per block (128 pairs): Y[128,128] = XI @ M (tf32 HMMA), then
// out_i = sum_j [ xu_ij*(Y_ij + v_j) + v_j*xi_ij ] + b.b
// Also clears g_mask for its 256 nodes (restores the all-zero invariant).
#define MS_OFF   0
#define XI_OFF   (DIM * S * 4)
#define XU_OFF   (2 * DIM * S * 4)
#define VV_OFF   (3 * DIM * S * 4)
#define NDI_OFF  (VV_OFF + 512)
#define NDU_OFF  (NDI_OFF + 512)
#define PART_OFF (NDU_OFF + 512)
#define SMEM_K3  (PART_OFF + 2048)

__global__ void __launch_bounds__(512) k_pairs(
    const int* __restrict__ ui, const int* __restrict__ ii,
    float* __restrict__ out)
{
    extern __shared__ char sm[];
    float* Msm  = (float*)(sm + MS_OFF);    // Msm[j][k] (symmetric M)
    float* XIs  = (float*)(sm + XI_OFF);    // XIs[i][k], tf32-rounded
    float* XUs  = (float*)(sm + XU_OFF);    // XUs[i][k], fp32
    float* Vv   = (float*)(sm + VV_OFF);
    int*   Ndi  = (int*)(sm + NDI_OFF);
    int*   Ndu  = (int*)(sm + NDU_OFF);
    float* Part = (float*)(sm + PART_OFF);  // [128][4]

    int tid = threadIdx.x, warp = tid >> 5, lane = tid & 31;
    int base = blockIdx.x * BPB;
    int g = lane >> 2, t = lane & 3;

    // stage node indices + v
    if (tid < 128) {
        Ndi[tid] = NUM_USERS + __ldg(&ii[base + tid]);
        Ndu[tid] = __ldg(&ui[base + tid]);
        Vv[tid]  = g_v[tid];
    }
    // stage M with restride; float4, conflict-free
    for (int idx = tid; idx < DIM * DIM / 4; idx += 512) {
        int r = idx >> 5, c4 = idx & 31;
        *(float4*)&Msm[r * S + 4 * c4] = ((const float4*)g_M)[idx];
    }
    __syncthreads();

    // flat gather: 8192 float4 slots (rows 0..127 = XI, 128..255 = XU);
    // each warp loads one contiguous 512B row per iter, 16 independent iters.
#pragma unroll
    for (int it = 0; it < 16; it++) {
        int idx = it * 512 + tid;
        int row = idx >> 5, f4 = idx & 31;
        if (row < 128) {
            int node = Ndi[row];
            float4 v = ((const float4*)(g_agg + (size_t)node * DIM))[f4];
            float* p = &XIs[row * S + 4 * f4];
            p[0] = tf32r(v.x); p[1] = tf32r(v.y); p[2] = tf32r(v.z); p[3] = tf32r(v.w);
        } else {
            int node = Ndu[row - 128];
            float4 v = ((const float4*)(g_agg + (size_t)node * DIM))[f4];
            *(float4*)&XUs[(row - 128) * S + 4 * f4] = v;
        }
    }
    __syncthreads();

    // clear mask for this block's nodes (restores invariant for next call)
    if (tid < 128) {
        g_mask[Ndi[tid]] = 0;
        g_mask[Ndu[tid]] = 0;
    }

    // warp tile: rows m0..m0+31, cols j0..j0+31
    int m0 = (warp & 3) * 32, j0 = (warp >> 2) * 32;
    float acc[2][4][4];
#pragma unroll
    for (int mi = 0; mi < 2; mi++)
#pragma unroll
        for (int ni = 0; ni < 4; ni++)
#pragma unroll
            for (int q = 0; q < 4; q++) acc[mi][ni][q] = 0.f;

#pragma unroll
    for (int k0 = 0; k0 < DIM; k0 += 8) {
        uint32_t a[2][4], b[4][2];
#pragma unroll
        for (int mi = 0; mi < 2; mi++) {
            const float* ap = XIs + (m0 + 16 * mi + g) * S + k0 + t;
            a[mi][0] = __float_as_uint(ap[0]);
            a[mi][1] = __float_as_uint(ap[8 * S]);
            a[mi][2] = __float_as_uint(ap[4]);
            a[mi][3] = __float_as_uint(ap[8 * S + 4]);
        }
#pragma unroll
        for (int ni = 0; ni < 4; ni++) {
            const float* bp = Msm + (j0 + 8 * ni + g) * S + k0 + t;
            b[ni][0] = __float_as_uint(bp[0]);
            b[ni][1] = __float_as_uint(bp[4]);
        }
#pragma unroll
        for (int mi = 0; mi < 2; mi++)
#pragma unroll
            for (int ni = 0; ni < 4; ni++)
                asm volatile(
                    "mma.sync.aligned.m16n8k8.row.col.f32.tf32.tf32.f32 "
                    "{%0,%1,%2,%3}, {%4,%5,%6,%7}, {%8,%9}, {%0,%1,%2,%3};"
                    : "+f"(acc[mi][ni][0]), "+f"(acc[mi][ni][1]),
                      "+f"(acc[mi][ni][2]), "+f"(acc[mi][ni][3])
                    : "r"(a[mi][0]), "r"(a[mi][1]), "r"(a[mi][2]), "r"(a[mi][3]),
                      "r"(b[ni][0]), "r"(b[ni][1]));
    }

    // epilogue: p_row = sum_j in warp tile of [xu*(y+v) + v*xi]; reduce over t
    int nw = warp >> 2;
#pragma unroll
    for (int mi = 0; mi < 2; mi++) {
        int r_lo = m0 + 16 * mi + g;
        int r_hi = r_lo + 8;
        float plo = 0.f, phi = 0.f;
#pragma unroll
        for (int ni = 0; ni < 4; ni++) {
            int j = j0 + 8 * ni + 2 * t;
            float2 vl  = *(const float2*)&Vv[j];
            float2 xul = *(const float2*)&XUs[r_lo * S + j];
            float2 xuh = *(const float2*)&XUs[r_hi * S + j];
            float2 xil = *(const float2*)&XIs[r_lo * S + j];
            float2 xih = *(const float2*)&XIs[r_hi * S + j];
            plo += xul.x * (acc[mi][ni][0] + vl.x) + xul.y * (acc[mi][ni][1] + vl.y)
                 + vl.x * xil.x + vl.y * xil.y;
            phi += xuh.x * (acc[mi][ni][2] + vl.x) + xuh.y * (acc[mi][ni][3] + vl.y)
                 + vl.x * xih.x + vl.y * xih.y;
        }
        plo += __shfl_xor_sync(0xffffffffu, plo, 1);
        plo += __shfl_xor_sync(0xffffffffu, plo, 2);
        phi += __shfl_xor_sync(0xffffffffu, phi, 1);
        phi += __shfl_xor_sync(0xffffffffu, phi, 2);
        if (t == 0) {
            Part[r_lo * 4 + nw] = plo;
            Part[r_hi * 4 + nw] = phi;
        }
    }
    __syncthreads();

    if (tid < BPB) {
        float r = Part[tid * 4 + 0] + Part[tid * 4 + 1]
                + Part[tid * 4 + 2] + Part[tid * 4 + 3];
        out[base + tid] = r + g_c;
    }
}

// ---------------- launch ----------------------------------------------------
extern "C" void kernel_launch(void* const* d_in, const int* in_sizes, int n_in,
                              void* d_out, int out_size) {
    const int*   ui   = (const int*)d_in[0];
    const int*   ii   = (const int*)d_in[1];
    const float* uemb = (const float*)d_in[2];
    const float* iemb = (const float*)d_in[3];
    const float* W    = (const float*)d_in[4];
    const float* b    = (const float*)d_in[5];
    const int*   ei   = (const int*)d_in[6];
    const int*   src  = ei;
    const int*   dst  = ei + NUM_EDGES;
    float*       out  = (float*)d_out;

    cudaFuncSetAttribute(k_pairs, cudaFuncAttributeMaxDynamicSharedMemorySize, SMEM_K3);

    k_pre<<<PREGRID, 256>>>(W, b, ui, ii);
    k_edge<<<(NUM_EDGES + 255) / 256, 256>>>(src, dst, uemb, iemb);
    k_pairs<<<BATCH / BPB, 512, SMEM_K3>>>(ui, ii, out);
}

// round 10
// speedup vs baseline: 1.0446x; 1.0446x over previous
#include <cuda_runtime.h>
#include <cuda_bf16.h>
#include <cstdint>

#define NUM_USERS 200000
#define NUM_ITEMS 100000
#define NUM_NODES (NUM_USERS + NUM_ITEMS)
#define NUM_EDGES 600000
#define DIM 128
#define BATCH 16384
#define BPB 128
#define S 132   // smem row stride (floats): conflict-free fragment access

// ---------------- scratch (static device globals) ---------------------------
// INVARIANT: g_mask is all-zero at entry to every kernel_launch call.
// (Zero-initialized at load; k_pairs clears every bit it set, every call.)
__device__ __align__(16) float g_agg[(size_t)NUM_NODES * DIM];
__device__ __align__(16) unsigned char g_mask[NUM_NODES];
__device__ __align__(16) float g_M[DIM * DIM];      // W^T W, tf32-rounded (symmetric)
__device__ __align__(16) float g_v[DIM];            // W^T b (fp32)
__device__ float g_c;                               // b.b

__device__ __forceinline__ float tf32r(float x) {
    unsigned u = __float_as_uint(x);
    u = (u + 0x1000u) & 0xFFFFE000u;
    return __uint_as_float(u);
}

// ---------------- K0 (fused): precompute (smem-staged W) + mark/zero rows ----
// blocks [0,64):          M rows 2b, 2b+1 (tf32) from smem W; block 0: v, c
// blocks [64, 64+1024):   mark needed nodes + zero their agg rows (4 rows/warp)
#define MBLOCKS 64
#define MARKBLOCKS (2 * BATCH / 32)             // 1024 (32 rows per block)
#define PREGRID (MBLOCKS + MARKBLOCKS)
#define SMEM_PRE (DIM * DIM * 4)                // 64KB W stage

__global__ void k_pre(const float* __restrict__ W, const float* __restrict__ b,
                      const int* __restrict__ ui, const int* __restrict__ ii) {
    extern __shared__ float Ws[];
    int blk = blockIdx.x, tid = threadIdx.x;
    if (blk < MBLOCKS) {
        // stage W into smem (coalesced float4; L2-broadcast across blocks)
        for (int idx = tid; idx < DIM * DIM / 4; idx += 256)
            ((float4*)Ws)[idx] = ((const float4*)W)[idx];
        __syncthreads();

        int r = 2 * blk + (tid >> 7);
        int c = tid & 127;
        // 4-way split accumulator to break the FADD chain
        float a0 = 0.f, a1 = 0.f, a2 = 0.f, a3 = 0.f;
#pragma unroll
        for (int j = 0; j < DIM; j += 4) {
            a0 += Ws[(j + 0) * DIM + r] * Ws[(j + 0) * DIM + c];
            a1 += Ws[(j + 1) * DIM + r] * Ws[(j + 1) * DIM + c];
            a2 += Ws[(j + 2) * DIM + r] * Ws[(j + 2) * DIM + c];
            a3 += Ws[(j + 3) * DIM + r] * Ws[(j + 3) * DIM + c];
        }
        g_M[r * DIM + c] = tf32r((a0 + a1) + (a2 + a3));

        if (blk == 0 && tid < 128) {
            float vv = 0.f;
#pragma unroll 8
            for (int j = 0; j < DIM; j++) vv += b[j] * Ws[j * DIM + c];
            g_v[c] = vv;
            if (tid == 0) {
                float s = 0.f;
#pragma unroll 8
                for (int j = 0; j < DIM; j++) s += b[j] * b[j];
                g_c = s;
            }
        }
    } else {
        // mark/zero: 8 warps x 4 rows = 32 rows per block
        int warp = tid >> 5, lane = tid & 31;
        int rowbase = (blk - MBLOCKS) * 32 + warp * 4;
        const float4 z = make_float4(0.f, 0.f, 0.f, 0.f);
#pragma unroll
        for (int q = 0; q < 4; q++) {
            int ref = rowbase + q;
            int node = (ref < BATCH) ? __ldg(&ui[ref])
                                     : (NUM_USERS + __ldg(&ii[ref - BATCH]));
            ((float4*)(g_agg + (size_t)node * DIM))[lane] = z;
            if (lane == 0) g_mask[node] = 1;
        }
    }
}

// ---------------- K1: scan edges, gather + vectorized scatter-add ------------
__global__ void k_edge(const int* __restrict__ src, const int* __restrict__ dst,
                       const float* __restrict__ uemb, const float* __restrict__ iemb) {
    int e = blockIdx.x * blockDim.x + threadIdx.x;
    int lane = threadIdx.x & 31;
    bool pass = false;
    int d = 0, s = 0;
    if (e < NUM_EDGES) {
        d = dst[e];
        pass = (g_mask[d] != 0);
        if (pass) s = src[e];
    }
    unsigned m = __ballot_sync(0xffffffffu, pass);
    while (m) {
        int bit = __ffs(m) - 1;
        m &= m - 1;
        int ds = __shfl_sync(0xffffffffu, d, bit);
        int ss = __shfl_sync(0xffffffffu, s, bit);
        const float* sp = (ss < NUM_USERS)
                            ? (uemb + (size_t)ss * DIM)
                            : (iemb + (size_t)(ss - NUM_USERS) * DIM);
        float4 v = ((const float4*)sp)[lane];
        float* a = g_agg + (size_t)ds * DIM + lane * 4;
        asm volatile("red.global.add.v4.f32 [%0], {%1, %2, %3, %4};"
                     :: "l"(a), "f"(v.x), "f"(v.y), "f"(v.z), "f"(v.w)
                     : "memory");
    }
}

// ---------------- K2: mma.sync tf32 GEMM + fused bilinear epilogue -----------
// Per block (128 pairs): Y[128,128] = XI @ M (tf32 HMMA), then
// out_i = sum_j [ xu_ij*(Y_ij + v_j) + v_j*xi_ij ] + b.b
// Also clears g_mask for its 256 nodes (restores the all-zero invariant).
#define MS_OFF   0
#define XI_OFF   (DIM * S * 4)
#define XU_OFF   (2 * DIM * S * 4)
#define VV_OFF   (3 * DIM * S * 4)
#define NDI_OFF  (VV_OFF + 512)
#define NDU_OFF  (NDI_OFF + 512)
#define PART_OFF (NDU_OFF + 512)
#define SMEM_K3  (PART_OFF + 2048)

__global__ void __launch_bounds__(512) k_pairs(
    const int* __restrict__ ui, const int* __restrict__ ii,
    float* __restrict__ out)
{
    extern __shared__ char sm[];
    float* Msm  = (float*)(sm + MS_OFF);    // Msm[j][k] (symmetric M)
    float* XIs  = (float*)(sm + XI_OFF);    // XIs[i][k], tf32-rounded
    float* XUs  = (float*)(sm + XU_OFF);    // XUs[i][k], fp32
    float* Vv   = (float*)(sm + VV_OFF);
    int*   Ndi  = (int*)(sm + NDI_OFF);
    int*   Ndu  = (int*)(sm + NDU_OFF);
    float* Part = (float*)(sm + PART_OFF);  // [128][4]

    int tid = threadIdx.x, warp = tid >> 5, lane = tid & 31;
    int base = blockIdx.x * BPB;
    int g = lane >> 2, t = lane & 3;

    // stage node indices + v
    if (tid < 128) {
        Ndi[tid] = NUM_USERS + __ldg(&ii[base + tid]);
        Ndu[tid] = __ldg(&ui[base + tid]);
        Vv[tid]  = g_v[tid];
    }
    // stage M with restride; float4, conflict-free
    for (int idx = tid; idx < DIM * DIM / 4; idx += 512) {
        int r = idx >> 5, c4 = idx & 31;
        *(float4*)&Msm[r * S + 4 * c4] = ((const float4*)g_M)[idx];
    }
    __syncthreads();

    // flat gather: 8192 float4 slots (rows 0..127 = XI, 128..255 = XU);
    // each warp loads one contiguous 512B row per iter, 16 independent iters.
#pragma unroll
    for (int it = 0; it < 16; it++) {
        int idx = it * 512 + tid;
        int row = idx >> 5, f4 = idx & 31;
        if (row < 128) {
            int node = Ndi[row];
            float4 v = ((const float4*)(g_agg + (size_t)node * DIM))[f4];
            float* p = &XIs[row * S + 4 * f4];
            p[0] = tf32r(v.x); p[1] = tf32r(v.y); p[2] = tf32r(v.z); p[3] = tf32r(v.w);
        } else {
            int node = Ndu[row - 128];
            float4 v = ((const float4*)(g_agg + (size_t)node * DIM))[f4];
            *(float4*)&XUs[(row - 128) * S + 4 * f4] = v;
        }
    }
    __syncthreads();

    // clear mask for this block's nodes (restores invariant for next call)
    if (tid < 128) {
        g_mask[Ndi[tid]] = 0;
        g_mask[Ndu[tid]] = 0;
    }

    // warp tile: rows m0..m0+31, cols j0..j0+31
    int m0 = (warp & 3) * 32, j0 = (warp >> 2) * 32;
    float acc[2][4][4];
#pragma unroll
    for (int mi = 0; mi < 2; mi++)
#pragma unroll
        for (int ni = 0; ni < 4; ni++)
#pragma unroll
            for (int q = 0; q < 4; q++) acc[mi][ni][q] = 0.f;

#pragma unroll
    for (int k0 = 0; k0 < DIM; k0 += 8) {
        uint32_t a[2][4], b[4][2];
#pragma unroll
        for (int mi = 0; mi < 2; mi++) {
            const float* ap = XIs + (m0 + 16 * mi + g) * S + k0 + t;
            a[mi][0] = __float_as_uint(ap[0]);
            a[mi][1] = __float_as_uint(ap[8 * S]);
            a[mi][2] = __float_as_uint(ap[4]);
            a[mi][3] = __float_as_uint(ap[8 * S + 4]);
        }
#pragma unroll
        for (int ni = 0; ni < 4; ni++) {
            const float* bp = Msm + (j0 + 8 * ni + g) * S + k0 + t;
            b[ni][0] = __float_as_uint(bp[0]);
            b[ni][1] = __float_as_uint(bp[4]);
        }
#pragma unroll
        for (int mi = 0; mi < 2; mi++)
#pragma unroll
            for (int ni = 0; ni < 4; ni++)
                asm volatile(
                    "mma.sync.aligned.m16n8k8.row.col.f32.tf32.tf32.f32 "
                    "{%0,%1,%2,%3}, {%4,%5,%6,%7}, {%8,%9}, {%0,%1,%2,%3};"
                    : "+f"(acc[mi][ni][0]), "+f"(acc[mi][ni][1]),
                      "+f"(acc[mi][ni][2]), "+f"(acc[mi][ni][3])
                    : "r"(a[mi][0]), "r"(a[mi][1]), "r"(a[mi][2]), "r"(a[mi][3]),
                      "r"(b[ni][0]), "r"(b[ni][1]));
    }

    // epilogue: p_row = sum_j in warp tile of [xu*(y+v) + v*xi]; reduce over t
    int nw = warp >> 2;
#pragma unroll
    for (int mi = 0; mi < 2; mi++) {
        int r_lo = m0 + 16 * mi + g;
        int r_hi = r_lo + 8;
        float plo = 0.f, phi = 0.f;
#pragma unroll
        for (int ni = 0; ni < 4; ni++) {
            int j = j0 + 8 * ni + 2 * t;
            float2 vl  = *(const float2*)&Vv[j];
            float2 xul = *(const float2*)&XUs[r_lo * S + j];
            float2 xuh = *(const float2*)&XUs[r_hi * S + j];
            float2 xil = *(const float2*)&XIs[r_lo * S + j];
            float2 xih = *(const float2*)&XIs[r_hi * S + j];
            plo += xul.x * (acc[mi][ni][0] + vl.x) + xul.y * (acc[mi][ni][1] + vl.y)
                 + vl.x * xil.x + vl.y * xil.y;
            phi += xuh.x * (acc[mi][ni][2] + vl.x) + xuh.y * (acc[mi][ni][3] + vl.y)
                 + vl.x * xih.x + vl.y * xih.y;
        }
        plo += __shfl_xor_sync(0xffffffffu, plo, 1);
        plo += __shfl_xor_sync(0xffffffffu, plo, 2);
        phi += __shfl_xor_sync(0xffffffffu, phi, 1);
        phi += __shfl_xor_sync(0xffffffffu, phi, 2);
        if (t == 0) {
            Part[r_lo * 4 + nw] = plo;
            Part[r_hi * 4 + nw] = phi;
        }
    }
    __syncthreads();

    if (tid < BPB) {
        float r = Part[tid * 4 + 0] + Part[tid * 4 + 1]
                + Part[tid * 4 + 2] + Part[tid * 4 + 3];
        out[base + tid] = r + g_c;
    }
}

// ---------------- launch ----------------------------------------------------
extern "C" void kernel_launch(void* const* d_in, const int* in_sizes, int n_in,
                              void* d_out, int out_size) {
    const int*   ui   = (const int*)d_in[0];
    const int*   ii   = (const int*)d_in[1];
    const float* uemb = (const float*)d_in[2];
    const float* iemb = (const float*)d_in[3];
    const float* W    = (const float*)d_in[4];
    const float* b    = (const float*)d_in[5];
    const int*   ei   = (const int*)d_in[6];
    const int*   src  = ei;
    const int*   dst  = ei + NUM_EDGES;
    float*       out  = (float*)d_out;

    cudaFuncSetAttribute(k_pre,   cudaFuncAttributeMaxDynamicSharedMemorySize, SMEM_PRE);
    cudaFuncSetAttribute(k_pairs, cudaFuncAttributeMaxDynamicSharedMemorySize, SMEM_K3);

    k_pre<<<PREGRID, 256, SMEM_PRE>>>(W, b, ui, ii);
    k_edge<<<(NUM_EDGES + 255) / 256, 256>>>(src, dst, uemb, iemb);
    k_pairs<<<BATCH / BPB, 512, SMEM_K3>>>(ui, ii, out);
}